// round 1
// baseline (speedup 1.0000x reference)
#include <cuda_runtime.h>

// ---------------- problem constants ----------------
#define NN    50000
#define EE    1600000
#define RR    8
#define NSEG  (NN*RR)        // 400000
#define DH    128
#define KDIM  1152           // 8*128 relation blocks + 128 root block
#define GG    64
#define NCLS  10

// ---------------- device scratch (allocation-free) ----------------
__device__ int   g_deg[NSEG];
__device__ int   g_offs[NSEG + 1];
__device__ int   g_cursor[NSEG];
__device__ int   g_eidx[EE];
__device__ float g_Z[(size_t)NN * KDIM];     // 230.4 MB
__device__ float g_H1[(size_t)NN * DH];
__device__ float g_H2[(size_t)NN * DH];
__device__ float g_W1c[KDIM * DH];
__device__ float g_W2c[KDIM * DH];
__device__ float g_gsum[GG * DH];
__device__ int   g_gcnt[GG];

// ---------------- f32x2 helpers (sm_100+) ----------------
__device__ __forceinline__ unsigned long long pack2(float x) {
    unsigned long long r;
    asm("mov.b64 %0, {%1, %1};" : "=l"(r) : "r"(__float_as_uint(x)));
    return r;
}
__device__ __forceinline__ void fma2(unsigned long long& d,
                                     unsigned long long a,
                                     unsigned long long b) {
    asm("fma.rn.f32x2 %0, %1, %2, %0;" : "+l"(d) : "l"(a), "l"(b));
}

// ---------------- CSR build ----------------
__global__ void k_zero() {
    int i = blockIdx.x * blockDim.x + threadIdx.x;
    if (i < NSEG)    g_deg[i] = 0;
    if (i < GG * DH) g_gsum[i] = 0.f;
    if (i < GG)      g_gcnt[i] = 0;
}

__global__ void k_count(const int* __restrict__ dst, const int* __restrict__ typ) {
    int e = blockIdx.x * blockDim.x + threadIdx.x;
    if (e < EE) atomicAdd(&g_deg[dst[e] * RR + typ[e]], 1);
}

// single-block 2-pass scan over NSEG elements
__global__ void k_scan() {
    __shared__ int sums[1024];
    const int CH = (NSEG + 1023) / 1024;      // 391
    int t = threadIdx.x;
    int b = t * CH;
    int e = min(b + CH, NSEG);
    int s = 0;
    for (int i = b; i < e; i++) s += g_deg[i];
    sums[t] = s;
    __syncthreads();
    // Hillis-Steele inclusive scan
    for (int off = 1; off < 1024; off <<= 1) {
        int v = (t >= off) ? sums[t - off] : 0;
        __syncthreads();
        sums[t] += v;
        __syncthreads();
    }
    int run = (t == 0) ? 0 : sums[t - 1];
    for (int i = b; i < e; i++) {
        g_offs[i] = run;
        g_cursor[i] = run;
        run += g_deg[i];
    }
    if (t == 1023) g_offs[NSEG] = run;
}

__global__ void k_fill(const int* __restrict__ src, const int* __restrict__ dst,
                       const int* __restrict__ typ) {
    int e = blockIdx.x * blockDim.x + threadIdx.x;
    if (e < EE) {
        int seg = dst[e] * RR + typ[e];
        int p = atomicAdd(&g_cursor[seg], 1);
        g_eidx[p] = src[e];
    }
}

// ---------------- Wcat = [W_flat ; root] ----------------
__global__ void k_wcat(const float* __restrict__ W, const float* __restrict__ root,
                       float* __restrict__ out) {
    int i = blockIdx.x * blockDim.x + threadIdx.x;
    const int WSZ = RR * DH * DH;             // 131072
    if (i < WSZ)            out[i] = W[i];
    else if (i < KDIM * DH) out[i] = root[i - WSZ];
}

// ---------------- aggregation: per-node warp, per-relation mean ----------------
__global__ void __launch_bounds__(256) k_aggregate(const float* __restrict__ feat) {
    int w = (blockIdx.x * blockDim.x + threadIdx.x) >> 5;
    int lane = threadIdx.x & 31;
    if (w >= NN) return;
    float* zrow = g_Z + (size_t)w * KDIM;
    // self feature into root block
    float4 self = *(const float4*)(feat + (size_t)w * DH + lane * 4);
    *(float4*)(zrow + RR * DH + lane * 4) = self;
    int base = w * RR;
#pragma unroll
    for (int r = 0; r < RR; r++) {
        int s = g_offs[base + r];
        int e = g_offs[base + r + 1];
        float4 acc = make_float4(0.f, 0.f, 0.f, 0.f);
        for (int i = s; i < e; i++) {
            const float4 v = *(const float4*)(feat + (size_t)g_eidx[i] * DH + lane * 4);
            acc.x += v.x; acc.y += v.y; acc.z += v.z; acc.w += v.w;
        }
        float inv = (e > s) ? 1.f / (float)(e - s) : 0.f;
        acc.x *= inv; acc.y *= inv; acc.z *= inv; acc.w *= inv;
        *(float4*)(zrow + r * DH + lane * 4) = acc;
    }
}

// ---------------- fp32 (f32x2) tiled GEMM: C[M,128] = A[M,K] @ B[K,128] + bias (+relu) ----------------
#define BM 128
#define BN 128
#define BK 16

__global__ void __launch_bounds__(256, 2)
k_gemm(const float* __restrict__ A, const float* __restrict__ B,
       const float* __restrict__ bias, float* __restrict__ C,
       int M, int K, int do_relu) {
    __shared__ float As[BK][BM];
    __shared__ float Bs[BK][BN];

    const int bm = blockIdx.x * BM;
    const int tid = threadIdx.x;
    const int tx = tid & 15;        // 16 cols of threads -> n
    const int ty = tid >> 4;        // 16 rows of threads -> m

    unsigned long long acc[8][4];
#pragma unroll
    for (int i = 0; i < 8; i++)
#pragma unroll
        for (int j = 0; j < 4; j++) acc[i][j] = 0ull;

    for (int k0 = 0; k0 < K; k0 += BK) {
        // load A tile (128 rows x 16 k), transpose into As[k][m]
#pragma unroll
        for (int it = 0; it < 2; it++) {
            int idx = tid + it * 256;          // 0..511
            int m = idx >> 2;
            int kk = (idx & 3) * 4;
            float4 v = make_float4(0.f, 0.f, 0.f, 0.f);
            int gm = bm + m;
            if (gm < M) v = *(const float4*)(A + (size_t)gm * K + k0 + kk);
            As[kk + 0][m] = v.x;
            As[kk + 1][m] = v.y;
            As[kk + 2][m] = v.z;
            As[kk + 3][m] = v.w;
        }
        // load B tile (16 k x 128 n)
#pragma unroll
        for (int it = 0; it < 2; it++) {
            int idx = tid + it * 256;
            int kk = idx >> 5;
            int n4 = (idx & 31) * 4;
            *(float4*)&Bs[kk][n4] = *(const float4*)(B + (size_t)(k0 + kk) * DH + n4);
        }
        __syncthreads();

#pragma unroll
        for (int kk = 0; kk < BK; kk++) {
            float4 a0 = *(const float4*)&As[kk][ty * 8];
            float4 a1 = *(const float4*)&As[kk][ty * 8 + 4];
            ulonglong2 b0 = *(const ulonglong2*)&Bs[kk][tx * 8];
            ulonglong2 b1 = *(const ulonglong2*)&Bs[kk][tx * 8 + 4];
            unsigned long long bp[4] = {b0.x, b0.y, b1.x, b1.y};
            float av[8] = {a0.x, a0.y, a0.z, a0.w, a1.x, a1.y, a1.z, a1.w};
#pragma unroll
            for (int i = 0; i < 8; i++) {
                unsigned long long ap = pack2(av[i]);
#pragma unroll
                for (int j = 0; j < 4; j++) fma2(acc[i][j], ap, bp[j]);
            }
        }
        __syncthreads();
    }

    // epilogue: unpack, +bias, relu, store
    const int row0 = bm + ty * 8;
    const int col0 = tx * 8;
    float bi[8];
#pragma unroll
    for (int j = 0; j < 8; j++) bi[j] = __ldg(bias + col0 + j);

#pragma unroll
    for (int i = 0; i < 8; i++) {
        int gm = row0 + i;
        if (gm >= M) continue;
        float o[8];
#pragma unroll
        for (int j = 0; j < 4; j++) {
            o[2 * j]     = __uint_as_float((unsigned)(acc[i][j] & 0xFFFFFFFFull));
            o[2 * j + 1] = __uint_as_float((unsigned)(acc[i][j] >> 32));
        }
#pragma unroll
        for (int j = 0; j < 8; j++) {
            float v = o[j] + bi[j];
            if (do_relu) v = fmaxf(v, 0.f);
            o[j] = v;
        }
        float4* cp = (float4*)(C + (size_t)gm * DH + col0);
        cp[0] = make_float4(o[0], o[1], o[2], o[3]);
        cp[1] = make_float4(o[4], o[5], o[6], o[7]);
    }
}

// ---------------- global mean pool ----------------
__global__ void __launch_bounds__(256) k_pool(const float* __restrict__ h,
                                              const int* __restrict__ batch) {
    int w = (blockIdx.x * blockDim.x + threadIdx.x) >> 5;
    int lane = threadIdx.x & 31;
    if (w >= NN) return;
    int g = batch[w];
    if (lane == 0) atomicAdd(&g_gcnt[g], 1);
    float4 v = *(const float4*)(h + (size_t)w * DH + lane * 4);
    float* dst = g_gsum + g * DH + lane * 4;
    atomicAdd(dst + 0, v.x);
    atomicAdd(dst + 1, v.y);
    atomicAdd(dst + 2, v.z);
    atomicAdd(dst + 3, v.w);
}

// ---------------- final linear ----------------
__global__ void k_final(const float* __restrict__ lw, const float* __restrict__ lb,
                        float* __restrict__ out) {
    int idx = threadIdx.x;
    if (idx >= GG * NCLS) return;
    int g = idx / NCLS, c = idx % NCLS;
    float inv = 1.f / fmaxf((float)g_gcnt[g], 1.f);
    float s = 0.f;
#pragma unroll 4
    for (int d = 0; d < DH; d++) s += g_gsum[g * DH + d] * inv * __ldg(lw + d * NCLS + c);
    out[idx] = s + __ldg(lb + c);
}

// ---------------- launch ----------------
extern "C" void kernel_launch(void* const* d_in, const int* in_sizes, int n_in,
                              void* d_out, int out_size) {
    const float* x     = (const float*)d_in[0];
    const int*   ei    = (const int*)d_in[1];     // [2,E]
    const int*   etype = (const int*)d_in[2];
    const int*   batch = (const int*)d_in[3];
    const float* W1    = (const float*)d_in[4];
    const float* root1 = (const float*)d_in[5];
    const float* b1    = (const float*)d_in[6];
    const float* W2    = (const float*)d_in[7];
    const float* root2 = (const float*)d_in[8];
    const float* b2    = (const float*)d_in[9];
    const float* lw    = (const float*)d_in[10];
    const float* lb    = (const float*)d_in[11];
    float* out = (float*)d_out;

    const int* src = ei;
    const int* dst = ei + EE;

    float *Z, *H1, *H2, *W1c, *W2c;
    cudaGetSymbolAddress((void**)&Z,   g_Z);
    cudaGetSymbolAddress((void**)&H1,  g_H1);
    cudaGetSymbolAddress((void**)&H2,  g_H2);
    cudaGetSymbolAddress((void**)&W1c, g_W1c);
    cudaGetSymbolAddress((void**)&W2c, g_W2c);

    const int TB = 256;
    // CSR build (shared by both layers)
    k_zero<<<(NSEG + TB - 1) / TB, TB>>>();
    k_count<<<(EE + TB - 1) / TB, TB>>>(dst, etype);
    k_scan<<<1, 1024>>>();
    k_fill<<<(EE + TB - 1) / TB, TB>>>(src, dst, etype);

    // weight concat
    k_wcat<<<(KDIM * DH + TB - 1) / TB, TB>>>(W1, root1, W1c);
    k_wcat<<<(KDIM * DH + TB - 1) / TB, TB>>>(W2, root2, W2c);

    const int aggBlocks = (NN * 32 + TB - 1) / TB;
    const int gemmBlocks = (NN + BM - 1) / BM;

    // layer 1
    k_aggregate<<<aggBlocks, TB>>>(x);
    k_gemm<<<gemmBlocks, TB>>>(Z, W1c, b1, H1, NN, KDIM, 1);
    // layer 2
    k_aggregate<<<aggBlocks, TB>>>(H1);
    k_gemm<<<gemmBlocks, TB>>>(Z, W2c, b2, H2, NN, KDIM, 1);

    // pool + classify
    k_pool<<<aggBlocks, TB>>>(H2, batch);
    k_final<<<1, GG * NCLS>>>(lw, lb, out);
}

// round 3
// speedup vs baseline: 3.0155x; 3.0155x over previous
#include <cuda_runtime.h>
#include <cstdint>

// ---------------- problem constants ----------------
#define NN    50000
#define EE    1600000
#define RR    8
#define NSEG  (NN*RR)        // 400000
#define DH    128
#define KDIM  1152           // 8*128 relation blocks + 128 root block
#define GG    64
#define NCLS  10

#define BM    128
#define BK    32
#define NCHUNK (KDIM/BK)     // 36

// smem tile layouts (floats): A [128][36] pad, B [32][132] pad
#define A_PAD 36
#define B_PAD 132
#define A_TILE_B (BM * A_PAD * 4)      // 18432
#define B_TILE_B (BK * B_PAD * 4)      // 16896
#define SMEM_GEMM_BYTES (2 * A_TILE_B + 2 * B_TILE_B)   // 70656

// ---------------- device scratch (allocation-free) ----------------
__device__ int   g_deg[NSEG];
__device__ int   g_offs[NSEG + 1];
__device__ int   g_cursor[NSEG];
__device__ int   g_bsum[512];
__device__ int   g_eidx[EE];
__device__ float g_Z[(size_t)NN * KDIM];     // 230.4 MB
__device__ float g_H1[(size_t)NN * DH];
__device__ float g_H2[(size_t)NN * DH];
__device__ float g_W1c[KDIM * DH];           // [K=1152][N=128]
__device__ float g_W2c[KDIM * DH];
__device__ float g_gsum[GG * DH];
__device__ int   g_gcnt[GG];

// ---------------- helpers ----------------
__device__ __forceinline__ uint32_t smem_to_u32(const void* p) {
    uint32_t a;
    asm("{ .reg .u64 t; cvta.to.shared.u64 t, %1; cvt.u32.u64 %0, t; }" : "=r"(a) : "l"(p));
    return a;
}
__device__ __forceinline__ uint32_t cvt_tf32(float f) {
    uint32_t o;
    asm("cvt.rna.tf32.f32 %0, %1;" : "=r"(o) : "f"(f));
    return o;
}
__device__ __forceinline__ void cp_async16(uint32_t dst, const void* src, uint32_t src_sz) {
    asm volatile("cp.async.cg.shared.global [%0], [%1], 16, %2;"
                 :: "r"(dst), "l"(src), "r"(src_sz));
}
#define CP_COMMIT() asm volatile("cp.async.commit_group;" ::: "memory")
#define CP_WAIT(n)  asm volatile("cp.async.wait_group %0;" :: "n"(n) : "memory")

__device__ __forceinline__ void mma_tf32(float* c, const uint32_t* a,
                                         uint32_t b0, uint32_t b1) {
    asm volatile(
        "mma.sync.aligned.m16n8k8.row.col.f32.tf32.tf32.f32 "
        "{%0,%1,%2,%3}, {%4,%5,%6,%7}, {%8,%9}, {%0,%1,%2,%3};"
        : "+f"(c[0]), "+f"(c[1]), "+f"(c[2]), "+f"(c[3])
        : "r"(a[0]), "r"(a[1]), "r"(a[2]), "r"(a[3]), "r"(b0), "r"(b1));
}

// ---------------- CSR build ----------------
__global__ void k_zero() {
    int i = blockIdx.x * blockDim.x + threadIdx.x;
    if (i < NSEG)    g_deg[i] = 0;
    if (i < GG * DH) g_gsum[i] = 0.f;
    if (i < GG)      g_gcnt[i] = 0;
}

__global__ void k_count(const int* __restrict__ dst, const int* __restrict__ typ) {
    int e = blockIdx.x * blockDim.x + threadIdx.x;
    if (e < EE) atomicAdd(&g_deg[dst[e] * RR + typ[e]], 1);
}

__global__ void __launch_bounds__(1024) k_scan_block() {
    __shared__ int wsum[32];
    int i = blockIdx.x * 1024 + threadIdx.x;
    int lane = threadIdx.x & 31, warp = threadIdx.x >> 5;
    int v = (i < NSEG) ? g_deg[i] : 0;
    int x = v;
#pragma unroll
    for (int o = 1; o < 32; o <<= 1) {
        int y = __shfl_up_sync(0xFFFFFFFFu, x, o);
        if (lane >= o) x += y;
    }
    if (lane == 31) wsum[warp] = x;
    __syncthreads();
    if (threadIdx.x < 32) {
        int y = wsum[threadIdx.x];
        int z = y;
#pragma unroll
        for (int o = 1; o < 32; o <<= 1) {
            int t = __shfl_up_sync(0xFFFFFFFFu, z, o);
            if (threadIdx.x >= o) z += t;
        }
        wsum[threadIdx.x] = z - y;
    }
    __syncthreads();
    int excl = x - v + wsum[warp];
    if (i < NSEG) g_offs[i] = excl;
    if (threadIdx.x == 1023) g_bsum[blockIdx.x] = excl + v;
}

__global__ void __launch_bounds__(512) k_scan_top(int nblk) {
    __shared__ int s[512];
    int t = threadIdx.x;
    int v = (t < nblk) ? g_bsum[t] : 0;
    s[t] = v;
    __syncthreads();
    for (int o = 1; o < 512; o <<= 1) {
        int y = (t >= o) ? s[t - o] : 0;
        __syncthreads();
        s[t] += y;
        __syncthreads();
    }
    if (t < nblk) g_bsum[t] = s[t] - v;
}

__global__ void __launch_bounds__(1024) k_scan_add() {
    int i = blockIdx.x * 1024 + threadIdx.x;
    if (i < NSEG) {
        int o = g_offs[i] + g_bsum[blockIdx.x];
        g_offs[i] = o;
        g_cursor[i] = o;
    }
    if (i == 0) g_offs[NSEG] = EE;
}

__global__ void k_fill(const int* __restrict__ src, const int* __restrict__ dst,
                       const int* __restrict__ typ) {
    int e = blockIdx.x * blockDim.x + threadIdx.x;
    if (e < EE) {
        int seg = dst[e] * RR + typ[e];
        int p = atomicAdd(&g_cursor[seg], 1);
        g_eidx[p] = src[e];
    }
}

// ---------------- Wcat = [W_flat ; root]  ([K][N] row-major, no transpose) ------
__global__ void k_wcat(const float* __restrict__ W, const float* __restrict__ root,
                       float* __restrict__ out) {
    int i = blockIdx.x * blockDim.x + threadIdx.x;
    const int WSZ = RR * DH * DH;             // 131072
    if (i < WSZ)            out[i] = W[i];
    else if (i < KDIM * DH) out[i] = root[i - WSZ];
}

// ---------------- aggregation: per-node warp, per-relation mean ----------------
__global__ void __launch_bounds__(256) k_aggregate(const float* __restrict__ feat) {
    int w = (blockIdx.x * blockDim.x + threadIdx.x) >> 5;
    int lane = threadIdx.x & 31;
    if (w >= NN) return;
    float* zrow = g_Z + (size_t)w * KDIM;
    float4 self = *(const float4*)(feat + (size_t)w * DH + lane * 4);
    *(float4*)(zrow + RR * DH + lane * 4) = self;
    int base = w * RR;
#pragma unroll
    for (int r = 0; r < RR; r++) {
        int s = g_offs[base + r];
        int e = g_offs[base + r + 1];
        float4 acc = make_float4(0.f, 0.f, 0.f, 0.f);
        for (int i = s; i < e; i++) {
            const float4 v = *(const float4*)(feat + (size_t)g_eidx[i] * DH + lane * 4);
            acc.x += v.x; acc.y += v.y; acc.z += v.z; acc.w += v.w;
        }
        float inv = (e > s) ? 1.f / (float)(e - s) : 0.f;
        acc.x *= inv; acc.y *= inv; acc.z *= inv; acc.w *= inv;
        *(float4*)(zrow + r * DH + lane * 4) = acc;
    }
}

// ---------------- tf32 mma.sync GEMM: C[M,128] = A[M,1152] @ B[1152,128] + bias (+relu)
// 256 threads = 8 warps as 4(m) x 2(n); warp tile 32x64; double-buffered cp.async.
__global__ void __launch_bounds__(256, 2)
k_gemm_mma(const float* __restrict__ A, const float* __restrict__ B,
           const float* __restrict__ bias, float* __restrict__ C,
           int M, int relu) {
    extern __shared__ __align__(16) char smem[];
    const uint32_t smem_u32 = smem_to_u32(smem);
    const int tid = threadIdx.x;
    const int wid = tid >> 5, lane = tid & 31;
    const int warp_m = wid & 3, warp_n = wid >> 2;
    const int g = lane >> 2, tig = lane & 3;
    const int bm = blockIdx.x * BM;

    const uint32_t aOff[2] = {0u, (uint32_t)A_TILE_B};
    const uint32_t bOff[2] = {(uint32_t)(2 * A_TILE_B), (uint32_t)(2 * A_TILE_B + B_TILE_B)};

    float acc[2][8][4];
#pragma unroll
    for (int i = 0; i < 2; i++)
#pragma unroll
        for (int j = 0; j < 8; j++)
#pragma unroll
            for (int q = 0; q < 4; q++) acc[i][j][q] = 0.f;

    // ---- tile loader (cp.async) ----
    auto load_tile = [&](int c, int buf) {
        // A: 128 rows x 32 floats -> As[row][k] pad 36 ; 1024 16B chunks
        const float* Ab = A + (size_t)c * BK;
#pragma unroll
        for (int it = 0; it < 4; it++) {
            int idx = tid + it * 256;
            int row = idx >> 3;
            int q = idx & 7;
            int gm = bm + row;
            uint32_t dst = smem_u32 + aOff[buf] + row * (A_PAD * 4) + q * 16;
            cp_async16(dst, Ab + (size_t)gm * KDIM + q * 4, (gm < M) ? 16u : 0u);
        }
        // B: 32 rows x 128 floats -> Bs[k][n] pad 132 ; 1024 16B chunks
        const float* Bb = B + (size_t)c * BK * DH;
#pragma unroll
        for (int it = 0; it < 4; it++) {
            int idx = tid + it * 256;
            int row = idx >> 5;
            int ch = idx & 31;
            uint32_t dst = smem_u32 + bOff[buf] + row * (B_PAD * 4) + ch * 16;
            cp_async16(dst, Bb + (size_t)row * DH + ch * 4, 16u);
        }
    };

    load_tile(0, 0);
    CP_COMMIT();

    const int mbase = warp_m * 32;
    const int nbase = warp_n * 64;

    for (int c = 0; c < NCHUNK; c++) {
        const int buf = c & 1;
        if (c + 1 < NCHUNK) {
            load_tile(c + 1, buf ^ 1);
            CP_COMMIT();
            CP_WAIT(1);
        } else {
            CP_WAIT(0);
        }
        __syncthreads();

        const float* As = (const float*)(smem + aOff[buf]);
        const float* Bs = (const float*)(smem + bOff[buf]);

#pragma unroll
        for (int s = 0; s < 4; s++) {
            const int k0 = s * 8;
            uint32_t a[2][4];
#pragma unroll
            for (int mt = 0; mt < 2; mt++) {
                int r0 = mbase + mt * 16 + g;
                a[mt][0] = cvt_tf32(As[r0 * A_PAD + k0 + tig]);
                a[mt][1] = cvt_tf32(As[(r0 + 8) * A_PAD + k0 + tig]);
                a[mt][2] = cvt_tf32(As[r0 * A_PAD + k0 + tig + 4]);
                a[mt][3] = cvt_tf32(As[(r0 + 8) * A_PAD + k0 + tig + 4]);
            }
#pragma unroll
            for (int nt = 0; nt < 8; nt++) {
                int n = nbase + nt * 8 + g;
                uint32_t b0 = cvt_tf32(Bs[(k0 + tig) * B_PAD + n]);
                uint32_t b1 = cvt_tf32(Bs[(k0 + tig + 4) * B_PAD + n]);
                mma_tf32(acc[0][nt], a[0], b0, b1);
                mma_tf32(acc[1][nt], a[1], b0, b1);
            }
        }
        __syncthreads();
    }

    // ---- epilogue: +bias, relu, store float2 pairs ----
#pragma unroll
    for (int nt = 0; nt < 8; nt++) {
        int col = nbase + nt * 8 + tig * 2;
        float b0 = __ldg(bias + col);
        float b1 = __ldg(bias + col + 1);
#pragma unroll
        for (int mt = 0; mt < 2; mt++) {
            int r0 = bm + mbase + mt * 16 + g;
#pragma unroll
            for (int h = 0; h < 2; h++) {       // h=0: rows r0, h=1: r0+8
                int gm = r0 + h * 8;
                if (gm >= M) continue;
                float v0 = acc[mt][nt][2 * h + 0] + b0;
                float v1 = acc[mt][nt][2 * h + 1] + b1;
                if (relu) { v0 = fmaxf(v0, 0.f); v1 = fmaxf(v1, 0.f); }
                *(float2*)(C + (size_t)gm * DH + col) = make_float2(v0, v1);
            }
        }
    }
}

// ---------------- global mean pool ----------------
__global__ void __launch_bounds__(256) k_pool(const float* __restrict__ h,
                                              const int* __restrict__ batch) {
    int w = (blockIdx.x * blockDim.x + threadIdx.x) >> 5;
    int lane = threadIdx.x & 31;
    if (w >= NN) return;
    int g = batch[w];
    if (lane == 0) atomicAdd(&g_gcnt[g], 1);
    float4 v = *(const float4*)(h + (size_t)w * DH + lane * 4);
    float* dst = g_gsum + g * DH + lane * 4;
    atomicAdd(dst + 0, v.x);
    atomicAdd(dst + 1, v.y);
    atomicAdd(dst + 2, v.z);
    atomicAdd(dst + 3, v.w);
}

// ---------------- final linear ----------------
__global__ void k_final(const float* __restrict__ lw, const float* __restrict__ lb,
                        float* __restrict__ out) {
    int idx = threadIdx.x;
    if (idx >= GG * NCLS) return;
    int g = idx / NCLS, c = idx % NCLS;
    float inv = 1.f / fmaxf((float)g_gcnt[g], 1.f);
    float s = 0.f;
#pragma unroll 4
    for (int d = 0; d < DH; d++) s += g_gsum[g * DH + d] * inv * __ldg(lw + d * NCLS + c);
    out[idx] = s + __ldg(lb + c);
}

// ---------------- launch ----------------
extern "C" void kernel_launch(void* const* d_in, const int* in_sizes, int n_in,
                              void* d_out, int out_size) {
    const float* x     = (const float*)d_in[0];
    const int*   ei    = (const int*)d_in[1];     // [2,E]
    const int*   etype = (const int*)d_in[2];
    const int*   batch = (const int*)d_in[3];
    const float* W1    = (const float*)d_in[4];
    const float* root1 = (const float*)d_in[5];
    const float* b1    = (const float*)d_in[6];
    const float* W2    = (const float*)d_in[7];
    const float* root2 = (const float*)d_in[8];
    const float* b2    = (const float*)d_in[9];
    const float* lw    = (const float*)d_in[10];
    const float* lb    = (const float*)d_in[11];
    float* out = (float*)d_out;

    const int* src = ei;
    const int* dst = ei + EE;

    float *Z, *H1, *H2, *W1c, *W2c;
    cudaGetSymbolAddress((void**)&Z,   g_Z);
    cudaGetSymbolAddress((void**)&H1,  g_H1);
    cudaGetSymbolAddress((void**)&H2,  g_H2);
    cudaGetSymbolAddress((void**)&W1c, g_W1c);
    cudaGetSymbolAddress((void**)&W2c, g_W2c);

    cudaFuncSetAttribute(k_gemm_mma, cudaFuncAttributeMaxDynamicSharedMemorySize,
                         SMEM_GEMM_BYTES);

    const int TB = 256;
    const int scanBlocks = (NSEG + 1023) / 1024;    // 391
    // CSR build (shared by both layers)
    k_zero<<<(NSEG + TB - 1) / TB, TB>>>();
    k_count<<<(EE + TB - 1) / TB, TB>>>(dst, etype);
    k_scan_block<<<scanBlocks, 1024>>>();
    k_scan_top<<<1, 512>>>(scanBlocks);
    k_scan_add<<<scanBlocks, 1024>>>();
    k_fill<<<(EE + TB - 1) / TB, TB>>>(src, dst, etype);

    // weight concat (rows already [K][N])
    k_wcat<<<(KDIM * DH + TB - 1) / TB, TB>>>(W1, root1, W1c);
    k_wcat<<<(KDIM * DH + TB - 1) / TB, TB>>>(W2, root2, W2c);

    const int aggBlocks = (NN * 32 + TB - 1) / TB;
    const int gemmBlocks = (NN + BM - 1) / BM;

    // layer 1
    k_aggregate<<<aggBlocks, TB>>>(x);
    k_gemm_mma<<<gemmBlocks, TB, SMEM_GEMM_BYTES>>>(Z, W1c, b1, H1, NN, 1);
    // layer 2
    k_aggregate<<<aggBlocks, TB>>>(H1);
    k_gemm_mma<<<gemmBlocks, TB, SMEM_GEMM_BYTES>>>(Z, W2c, b2, H2, NN, 1);

    // pool + classify
    k_pool<<<aggBlocks, TB>>>(H2, batch);
    k_final<<<1, GG * NCLS>>>(lw, lb, out);
}